// round 1
// baseline (speedup 1.0000x reference)
#include <cuda_runtime.h>
#include <cstdint>

#define D_MODEL 2048
#define BATCH   16384
#define MT 128   // rows per CTA
#define NT 64    // output cols per CTA
#define AT 32    // angle cols per CTA (NT/2)
#define DT 8     // decay pad cols (col 0 real, 1..7 zero)
#define KC 32    // K chunk
#define LDK 36   // KC + 4 pad (conflict-free)
#define ANG_LD 33

__device__ __forceinline__ float to_tf32(float x) {
    float y;
    asm("cvt.rna.tf32.f32 %0, %1;" : "=f"(y) : "f"(x));
    return y;
}

__device__ __forceinline__ void mma_tf32(float* c, const uint32_t* a, const uint32_t* b) {
    asm volatile(
        "mma.sync.aligned.m16n8k8.row.col.f32.tf32.tf32.f32 "
        "{%0,%1,%2,%3}, {%4,%5,%6,%7}, {%8,%9}, {%0,%1,%2,%3};\n"
        : "+f"(c[0]), "+f"(c[1]), "+f"(c[2]), "+f"(c[3])
        : "r"(a[0]), "r"(a[1]), "r"(a[2]), "r"(a[3]), "r"(b[0]), "r"(b[1]));
}

__global__ __launch_bounds__(256) void givens_fused(
    const float* __restrict__ x, const float* __restrict__ h_prev,
    const float* __restrict__ W_angle, const float* __restrict__ b_angle,
    const float* __restrict__ W_decay, const float* __restrict__ b_decay,
    const float* __restrict__ W_in, const float* __restrict__ b_in,
    float* __restrict__ out)
{
    // SMEM: A tile, B tiles (inj/ang/dec), decay row buffer. Angle buffer
    // reuses the A-tile region after the mainloop.
    __shared__ float smem[MT*LDK + NT*LDK + AT*LDK + DT*LDK + MT];
    float* As     = smem;
    float* Bi     = As + MT*LDK;
    float* Ba     = Bi + NT*LDK;
    float* Bd     = Ba + AT*LDK;
    float* dec_sm = Bd + DT*LDK;
    float* ang_sm = As;                // valid only after mainloop + syncthreads

    const int tid  = threadIdx.x;
    const int warp = tid >> 5, lane = tid & 31;
    const int g    = lane >> 2, tg = lane & 3;       // mma group / thread-in-group
    const int wm   = warp >> 1, wn = warp & 1;       // 4x2 warp grid
    const int m0   = blockIdx.y * MT;
    const int n0   = blockIdx.x * NT;
    const int a0   = n0 >> 1;                        // first angle (pair) column

    float ci[2][4][4] = {};   // injection accum: warp covers 32x32
    float ca[2][2][4] = {};   // angle accum:     warp covers 32x16
    float cd[4]       = {};   // decay accum:     warp covers 16x8 (col 0 real)

    // zero the decay B pad once (rows 1..7 stay zero forever)
    for (int i = tid; i < DT*LDK; i += 256) Bd[i] = 0.f;

    const int lr = tid >> 3;          // 0..31
    const int lc = (tid & 7) * 4;     // 0,4,..,28

    for (int kc0 = 0; kc0 < D_MODEL; kc0 += KC) {
        __syncthreads();
        // A tile: 128x32, round-to-nearest tf32 (truncation would bias ~2^-10!)
        #pragma unroll
        for (int r = 0; r < 4; r++) {
            int row = lr + r*32;
            float4 v = *(const float4*)&x[(size_t)(m0+row)*D_MODEL + kc0 + lc];
            As[row*LDK+lc+0]=to_tf32(v.x); As[row*LDK+lc+1]=to_tf32(v.y);
            As[row*LDK+lc+2]=to_tf32(v.z); As[row*LDK+lc+3]=to_tf32(v.w);
        }
        // injection B tile: 64x32
        #pragma unroll
        for (int r = 0; r < 2; r++) {
            int row = lr + r*32;
            float4 v = *(const float4*)&W_in[(size_t)(n0+row)*D_MODEL + kc0 + lc];
            Bi[row*LDK+lc+0]=to_tf32(v.x); Bi[row*LDK+lc+1]=to_tf32(v.y);
            Bi[row*LDK+lc+2]=to_tf32(v.z); Bi[row*LDK+lc+3]=to_tf32(v.w);
        }
        // angle B tile: 32x32
        {
            float4 v = *(const float4*)&W_angle[(size_t)(a0+lr)*D_MODEL + kc0 + lc];
            Ba[lr*LDK+lc+0]=to_tf32(v.x); Ba[lr*LDK+lc+1]=to_tf32(v.y);
            Ba[lr*LDK+lc+2]=to_tf32(v.z); Ba[lr*LDK+lc+3]=to_tf32(v.w);
        }
        // decay B row 0
        if (tid < 8) {
            float4 v = *(const float4*)&W_decay[kc0 + tid*4];
            Bd[tid*4+0]=to_tf32(v.x); Bd[tid*4+1]=to_tf32(v.y);
            Bd[tid*4+2]=to_tf32(v.z); Bd[tid*4+3]=to_tf32(v.w);
        }
        __syncthreads();

        #pragma unroll
        for (int k8 = 0; k8 < 4; k8++) {
            const int k = k8*8;
            uint32_t a[2][4];
            #pragma unroll
            for (int mi = 0; mi < 2; mi++) {        // A frags shared by inj+ang
                int rm = wm*32 + mi*16;
                a[mi][0] = __float_as_uint(As[(rm+g  )*LDK + k+tg]);
                a[mi][1] = __float_as_uint(As[(rm+8+g)*LDK + k+tg]);
                a[mi][2] = __float_as_uint(As[(rm+g  )*LDK + k+tg+4]);
                a[mi][3] = __float_as_uint(As[(rm+8+g)*LDK + k+tg+4]);
            }
            #pragma unroll
            for (int ni = 0; ni < 4; ni++) {        // injection 32x32
                int nb = wn*32 + ni*8;
                uint32_t b[2];
                b[0] = __float_as_uint(Bi[(nb+g)*LDK + k+tg]);
                b[1] = __float_as_uint(Bi[(nb+g)*LDK + k+tg+4]);
                mma_tf32(ci[0][ni], a[0], b);
                mma_tf32(ci[1][ni], a[1], b);
            }
            #pragma unroll
            for (int ni = 0; ni < 2; ni++) {        // angles 32x16
                int nb = wn*16 + ni*8;
                uint32_t b[2];
                b[0] = __float_as_uint(Ba[(nb+g)*LDK + k+tg]);
                b[1] = __float_as_uint(Ba[(nb+g)*LDK + k+tg+4]);
                mma_tf32(ca[0][ni], a[0], b);
                mma_tf32(ca[1][ni], a[1], b);
            }
            {                                        // decay: 16 rows per warp
                int rm = warp*16;
                uint32_t ad[4], bd2[2];
                ad[0] = __float_as_uint(As[(rm+g  )*LDK + k+tg]);
                ad[1] = __float_as_uint(As[(rm+8+g)*LDK + k+tg]);
                ad[2] = __float_as_uint(As[(rm+g  )*LDK + k+tg+4]);
                ad[3] = __float_as_uint(As[(rm+8+g)*LDK + k+tg+4]);
                bd2[0] = __float_as_uint(Bd[g*LDK + k+tg]);
                bd2[1] = __float_as_uint(Bd[g*LDK + k+tg+4]);
                mma_tf32(cd, ad, bd2);
            }
        }
    }

    __syncthreads();
    // decay -> smem (only tg==0 holds column 0 of the dec tile)
    const float bdec = b_decay[0];
    if (tg == 0) {
        int r0 = warp*16 + g;
        dec_sm[r0]   = 1.f / (1.f + __expf(-(cd[0] + bdec)));
        dec_sm[r0+8] = 1.f / (1.f + __expf(-(cd[2] + bdec)));
    }
    // angles (+bias) -> smem, reusing the A-tile region
    #pragma unroll
    for (int mi = 0; mi < 2; mi++)
    #pragma unroll
    for (int ni = 0; ni < 2; ni++) {
        int rm = wm*32 + mi*16 + g;
        int cb = wn*16 + ni*8 + 2*tg;
        float bA0 = b_angle[a0 + cb];
        float bA1 = b_angle[a0 + cb + 1];
        ang_sm[ rm   *ANG_LD + cb  ] = ca[mi][ni][0] + bA0;
        ang_sm[ rm   *ANG_LD + cb+1] = ca[mi][ni][1] + bA1;
        ang_sm[(rm+8)*ANG_LD + cb  ] = ca[mi][ni][2] + bA0;
        ang_sm[(rm+8)*ANG_LD + cb+1] = ca[mi][ni][3] + bA1;
    }
    __syncthreads();

    // epilogue: out = decay * rotate(h_prev, theta) + injection + b_in
    #pragma unroll
    for (int mi = 0; mi < 2; mi++)
    #pragma unroll
    for (int ni = 0; ni < 4; ni++) {
        int cloc = wn*32 + ni*8 + 2*tg;              // even -> c0/c1 share a pair
        float2 bi2 = *(const float2*)&b_in[n0 + cloc];
        #pragma unroll
        for (int h = 0; h < 2; h++) {
            int rloc = wm*32 + mi*16 + g + h*8;
            size_t goff = (size_t)(m0+rloc)*D_MODEL + n0 + cloc;
            float theta = ang_sm[rloc*ANG_LD + (cloc>>1)];
            float sn, cs;
            __sincosf(theta, &sn, &cs);
            float2 hp = *(const float2*)&h_prev[goff];
            float d = dec_sm[rloc];
            float2 o;
            o.x = d*(cs*hp.x - sn*hp.y) + ci[mi][ni][h*2+0] + bi2.x;
            o.y = d*(sn*hp.x + cs*hp.y) + ci[mi][ni][h*2+1] + bi2.y;
            *(float2*)&out[goff] = o;
        }
    }
}

extern "C" void kernel_launch(void* const* d_in, const int* in_sizes, int n_in,
                              void* d_out, int out_size) {
    const float* x       = (const float*)d_in[0];
    const float* h_prev  = (const float*)d_in[1];
    const float* W_angle = (const float*)d_in[2];
    const float* b_angle = (const float*)d_in[3];
    const float* W_decay = (const float*)d_in[4];
    const float* b_decay = (const float*)d_in[5];
    const float* W_in    = (const float*)d_in[6];
    const float* b_in    = (const float*)d_in[7];
    dim3 grid(D_MODEL / NT, BATCH / MT);
    givens_fused<<<grid, 256>>>(x, h_prev, W_angle, b_angle, W_decay, b_decay,
                                W_in, b_in, (float*)d_out);
}

// round 3
// speedup vs baseline: 1.8218x; 1.8218x over previous
#include <cuda_runtime.h>
#include <cstdint>

#define D_MODEL 2048
#define BATCH   16384
#define MT 128
#define NT 64
#define STAGE_BYTES 29696        // A 16KB + B 13.3KB
#define SM_DEC (3*STAGE_BYTES)   // 89088
#define SMEM_TOTAL (SM_DEC + 512)

// scratch: x in A-fragment order, weights in B-fragment order
__device__ float g_xA[33554432];   // [rt 0..1023][t 0..255][lane][4]
__device__ float g_WB[6815744];    // [cb 0..31][bt 0..12][t 0..255][lane][2]

__device__ __forceinline__ float tf32r(float x) {
    float y; asm("cvt.rna.tf32.f32 %0, %1;" : "=f"(y) : "f"(x)); return y;
}
__device__ __forceinline__ uint32_t smem_u32(const void* p) {
    uint32_t a;
    asm("{ .reg .u64 t; cvta.to.shared.u64 t, %1; cvt.u32.u64 %0, t; }" : "=r"(a) : "l"(p));
    return a;
}
__device__ __forceinline__ void cp16(uint32_t dst, const void* src) {
    asm volatile("cp.async.cg.shared.global [%0], [%1], 16;" :: "r"(dst), "l"(src));
}
__device__ __forceinline__ void lds128(uint32_t* r, uint32_t a) {
    asm volatile("ld.shared.v4.b32 {%0,%1,%2,%3}, [%4];"
                 : "=r"(r[0]), "=r"(r[1]), "=r"(r[2]), "=r"(r[3]) : "r"(a));
}
__device__ __forceinline__ void lds64(uint32_t* r, uint32_t a) {
    asm volatile("ld.shared.v2.b32 {%0,%1}, [%2];" : "=r"(r[0]), "=r"(r[1]) : "r"(a));
}
__device__ __forceinline__ void mma_tf32(float* c, const uint32_t* a, const uint32_t* b) {
    asm volatile(
        "mma.sync.aligned.m16n8k8.row.col.f32.tf32.tf32.f32 "
        "{%0,%1,%2,%3}, {%4,%5,%6,%7}, {%8,%9}, {%0,%1,%2,%3};\n"
        : "+f"(c[0]), "+f"(c[1]), "+f"(c[2]), "+f"(c[3])
        : "r"(a[0]), "r"(a[1]), "r"(a[2]), "r"(a[3]), "r"(b[0]), "r"(b[1]));
}

// ---- preround: x -> A-fragment order (rna tf32) ----
__global__ void preround_x(const float* __restrict__ x) {
    size_t f = (size_t)blockIdx.x * 256 + threadIdx.x;      // 33554432 total
    int rt = (int)(f >> 15); int rem = (int)(f & 32767);
    int t = rem >> 7; int w = rem & 127;
    int lane = w >> 2, j = w & 3, g = lane >> 2, tg = lane & 3;
    int row = rt * 16 + g + ((j & 1) << 3);
    int col = t * 8 + tg + ((j >> 1) << 2);
    g_xA[f] = tf32r(x[(size_t)row * D_MODEL + col]);
}
// ---- preround: W_in/W_angle/W_decay -> concatenated B-fragment order ----
__global__ void preround_w(const float* __restrict__ Wi, const float* __restrict__ Wa,
                           const float* __restrict__ Wd) {
    size_t f = (size_t)blockIdx.x * 256 + threadIdx.x;      // 6815744 total
    int cb = (int)(f / 212992); int rem = (int)(f % 212992);
    int bt = rem >> 14; int rem2 = rem & 16383;
    int t = rem2 >> 6; int w = rem2 & 63;
    int lane = w >> 1, j = w & 1, g = lane >> 2, tg = lane & 3;
    int k = t * 8 + tg + 4 * j;
    float v;
    if (bt < 8)       v = Wi[(size_t)(cb * 64 + bt * 8 + g) * D_MODEL + k];
    else if (bt < 12) v = Wa[(size_t)(cb * 32 + (bt - 8) * 8 + g) * D_MODEL + k];
    else              v = (g == 0) ? Wd[k] : 0.f;
    g_WB[f] = tf32r(v);
}

// ---- main fused kernel: 128 threads, 4 warps (2x2), 3-stage cp.async ----
__global__ void __launch_bounds__(128, 2) givens_main(
    const float* __restrict__ h_prev, const float* __restrict__ b_angle,
    const float* __restrict__ b_decay, const float* __restrict__ b_in,
    float* __restrict__ out)
{
    extern __shared__ __align__(1024) char smem[];
    const uint32_t sb = smem_u32(smem);
    const int tid = threadIdx.x, warp = tid >> 5, lane = tid & 31;
    const int g = lane >> 2, tg = lane & 3;
    const int wm = warp >> 1, wn = warp & 1;            // 2x2 warp grid
    const int by = blockIdx.y, cb = blockIdx.x;
    const int m0 = by * MT, n0 = cb * NT, a0 = n0 >> 1;

    // per-thread cp.async source bases (bytes)
    const char* xA = (const char*)g_xA;
    const char* WB = (const char*)g_WB;
    const size_t axbase = (size_t)by * 1048576 + (size_t)warp * 512 + lane * 16;
    const size_t wbbase = (size_t)cb * 851968 + (size_t)(tid >> 6) * 65536
                        + ((tid >> 4) & 3) * 256 + (tid & 15) * 16;
    const bool btail = (tid < 64);

    float ci[4][4][4] = {};   // mi, nb, frag  (64 outputs cols wn*32+nb*8+2tg)
    float ca[4][2][4] = {};   // mi, na, frag  (angle pairs wn*16+na*8+2tg)
    float cd[4][4]    = {};   // mi, frag      (decay, wn==0 only)

    #define ISSUE(CHUNK, STG) do {                                              \
        uint32_t sd = sb + (STG) * STAGE_BYTES;                                 \
        const char* xs = xA + axbase + (size_t)(CHUNK) * 2048;                  \
        const char* ws = WB + wbbase + (size_t)(CHUNK) * 1024;                  \
        _Pragma("unroll")                                                       \
        for (int it = 0; it < 8; it++)                                          \
            cp16(sd + tid * 16 + it * 2048, xs + (size_t)it * 131072);          \
        _Pragma("unroll")                                                       \
        for (int ib = 0; ib < 7; ib++)                                          \
            if (ib < 6 || btail)                                                \
                cp16(sd + 16384 + ib * 2048 + tid * 16, ws + (size_t)ib * 131072); \
        asm volatile("cp.async.commit_group;" ::: "memory");                    \
    } while (0)

    ISSUE(0, 0);
    ISSUE(1, 1);

    #pragma unroll 1
    for (int c = 0; c < 64; c++) {
        asm volatile("cp.async.wait_group 1;" ::: "memory");
        __syncthreads();
        if (c + 2 < 64) { ISSUE(c + 2, (c + 2) % 3); }
        else            { asm volatile("cp.async.commit_group;" ::: "memory"); }

        const uint32_t sa = sb + (c % 3) * STAGE_BYTES;
        #pragma unroll
        for (int kt = 0; kt < 4; kt++) {
            uint32_t a[4][4];
            #pragma unroll
            for (int mi = 0; mi < 4; mi++)
                lds128(a[mi], sa + (uint32_t)(((wm * 4 + mi) * 4 + kt) * 512) + lane * 16);
            #pragma unroll
            for (int nb = 0; nb < 4; nb++) {
                uint32_t b[2];
                lds64(b, sa + 16384 + (uint32_t)(((wn * 4 + nb) * 4 + kt) * 256) + lane * 8);
                #pragma unroll
                for (int mi = 0; mi < 4; mi++) mma_tf32(ci[mi][nb], a[mi], b);
            }
            #pragma unroll
            for (int na = 0; na < 2; na++) {
                uint32_t b[2];
                lds64(b, sa + 16384 + (uint32_t)(((8 + wn * 2 + na) * 4 + kt) * 256) + lane * 8);
                #pragma unroll
                for (int mi = 0; mi < 4; mi++) mma_tf32(ca[mi][na], a[mi], b);
            }
            if (wn == 0) {
                uint32_t b[2];
                lds64(b, sa + 16384 + (uint32_t)((12 * 4 + kt) * 256) + lane * 8);
                #pragma unroll
                for (int mi = 0; mi < 4; mi++) mma_tf32(cd[mi], a[mi], b);
            }
        }
    }
    __syncthreads();

    // ---- epilogue ----
    float* ang_sm = (float*)smem;                       // 128 x 33 floats (stage0 reuse)
    float* dec_sm = (float*)(smem + SM_DEC);            // 128 floats
    const float bdec = b_decay[0];
    if (wn == 0 && tg == 0) {
        #pragma unroll
        for (int mi = 0; mi < 4; mi++) {
            int r = wm * 64 + mi * 16 + g;
            dec_sm[r]     = 1.f / (1.f + __expf(-(cd[mi][0] + bdec)));
            dec_sm[r + 8] = 1.f / (1.f + __expf(-(cd[mi][2] + bdec)));
        }
    }
    #pragma unroll
    for (int mi = 0; mi < 4; mi++)
    #pragma unroll
    for (int na = 0; na < 2; na++) {
        int rm  = wm * 64 + mi * 16 + g;
        int cbp = wn * 16 + na * 8 + 2 * tg;
        float bA0 = b_angle[a0 + cbp], bA1 = b_angle[a0 + cbp + 1];
        ang_sm[ rm      * 33 + cbp    ] = ca[mi][na][0] + bA0;
        ang_sm[ rm      * 33 + cbp + 1] = ca[mi][na][1] + bA1;
        ang_sm[(rm + 8) * 33 + cbp    ] = ca[mi][na][2] + bA0;
        ang_sm[(rm + 8) * 33 + cbp + 1] = ca[mi][na][3] + bA1;
    }
    __syncthreads();

    #pragma unroll
    for (int mi = 0; mi < 4; mi++)
    #pragma unroll
    for (int nb = 0; nb < 4; nb++) {
        int cloc = wn * 32 + nb * 8 + 2 * tg;
        float2 bi2 = *(const float2*)&b_in[n0 + cloc];
        #pragma unroll
        for (int h = 0; h < 2; h++) {
            int rloc = wm * 64 + mi * 16 + g + h * 8;
            size_t goff = (size_t)(m0 + rloc) * D_MODEL + n0 + cloc;
            float theta = ang_sm[rloc * 33 + (cloc >> 1)];
            float sn, cs;
            __sincosf(theta, &sn, &cs);
            float2 hp = *(const float2*)&h_prev[goff];
            float d = dec_sm[rloc];
            float2 o;
            o.x = d * (cs * hp.x - sn * hp.y) + ci[mi][nb][h * 2 + 0] + bi2.x;
            o.y = d * (sn * hp.x + cs * hp.y) + ci[mi][nb][h * 2 + 1] + bi2.y;
            *(float2*)&out[goff] = o;
        }
    }
    #undef ISSUE
}

extern "C" void kernel_launch(void* const* d_in, const int* in_sizes, int n_in,
                              void* d_out, int out_size) {
    const float* x       = (const float*)d_in[0];
    const float* h_prev  = (const float*)d_in[1];
    const float* W_angle = (const float*)d_in[2];
    const float* b_angle = (const float*)d_in[3];
    const float* W_decay = (const float*)d_in[4];
    const float* b_decay = (const float*)d_in[5];
    const float* W_in    = (const float*)d_in[6];
    const float* b_in    = (const float*)d_in[7];

    preround_x<<<131072, 256>>>(x);
    preround_w<<<26624, 256>>>(W_in, W_angle, W_decay);

    static bool attr_done = false;
    if (!attr_done) {
        cudaFuncSetAttribute(givens_main, cudaFuncAttributeMaxDynamicSharedMemorySize, SMEM_TOTAL);
        attr_done = true;
    }
    dim3 grid(D_MODEL / NT, BATCH / MT);
    givens_main<<<grid, 128, SMEM_TOTAL>>>(h_prev, b_angle, b_decay, b_in, (float*)d_out);
}